// round 1
// baseline (speedup 1.0000x reference)
#include <cuda_runtime.h>

#define NB 16
#define HH 512
#define WW 512
#define HQ 256
#define WQ 256
#define RAD 7
#define KS  15

#define TX 32
#define TY 32
#define TW (TX + 2*RAD)   // 46
#define TH (TY + 2*RAD)   // 46

// Scratch (device globals: no allocation allowed in kernel_launch)
__device__ float  g_yd[NB * HH * WW];
__device__ float  g_ud[NB * HQ * WQ];
__device__ float  g_vd[NB * HQ * WQ];
__device__ double g_acc[3];

__global__ void k_zero() {
    if (threadIdx.x < 3) g_acc[threadIdx.x] = 0.0;
}

// Compute YUV420 channels of (input - target). One thread per 2x2 block.
__global__ void k_diff(const float* __restrict__ in, const float* __restrict__ tg) {
    int idx = blockIdx.x * blockDim.x + threadIdx.x;   // over NB*HQ*WQ
    if (idx >= NB * HQ * WQ) return;
    int wq = idx & (WQ - 1);
    int hq = (idx >> 8) & (HQ - 1);
    int n  = idx >> 16;

    const long plane = (long)HH * WW;
    long base = (long)n * 3 * plane + (long)(2 * hq) * WW + 2 * wq;

    float y00, y01, y10, y11;
    float usum = 0.f, vsum = 0.f;

    {
        float2 ri = *(const float2*)(in + base);
        float2 gi = *(const float2*)(in + base + plane);
        float2 bi = *(const float2*)(in + base + 2 * plane);
        float2 rt = *(const float2*)(tg + base);
        float2 gt = *(const float2*)(tg + base + plane);
        float2 bt = *(const float2*)(tg + base + 2 * plane);
        float dr0 = ri.x - rt.x, dr1 = ri.y - rt.y;
        float dg0 = gi.x - gt.x, dg1 = gi.y - gt.y;
        float db0 = bi.x - bt.x, db1 = bi.y - bt.y;
        y00 = 0.299f * dr0 + 0.587f * dg0 + 0.114f * db0;
        y01 = 0.299f * dr1 + 0.587f * dg1 + 0.114f * db1;
        usum += -0.169f * (dr0 + dr1) - 0.331f * (dg0 + dg1) + 0.5f  * (db0 + db1);
        vsum +=  0.5f   * (dr0 + dr1) - 0.46f  * (dg0 + dg1) - 0.04f * (db0 + db1);
    }
    {
        long off = base + WW;
        float2 ri = *(const float2*)(in + off);
        float2 gi = *(const float2*)(in + off + plane);
        float2 bi = *(const float2*)(in + off + 2 * plane);
        float2 rt = *(const float2*)(tg + off);
        float2 gt = *(const float2*)(tg + off + plane);
        float2 bt = *(const float2*)(tg + off + 2 * plane);
        float dr0 = ri.x - rt.x, dr1 = ri.y - rt.y;
        float dg0 = gi.x - gt.x, dg1 = gi.y - gt.y;
        float db0 = bi.x - bt.x, db1 = bi.y - bt.y;
        y10 = 0.299f * dr0 + 0.587f * dg0 + 0.114f * db0;
        y11 = 0.299f * dr1 + 0.587f * dg1 + 0.114f * db1;
        usum += -0.169f * (dr0 + dr1) - 0.331f * (dg0 + dg1) + 0.5f  * (db0 + db1);
        vsum +=  0.5f   * (dr0 + dr1) - 0.46f  * (dg0 + dg1) - 0.04f * (db0 + db1);
    }

    long ybase = (long)n * plane + (long)(2 * hq) * WW + 2 * wq;
    *(float2*)(g_yd + ybase)      = make_float2(y00, y01);
    *(float2*)(g_yd + ybase + WW) = make_float2(y10, y11);
    g_ud[idx] = 0.25f * usum;
    g_vd[idx] = 0.25f * vsum;
}

// Separable 15x15 box filter (zero-pad SAME) + square + global reduce.
// One block = one 32x32 output tile. 1024 threads.
__global__ void __launch_bounds__(1024, 1)
k_filter(const float* __restrict__ src, int Hd, int Wd, int accIdx) {
    __shared__ float s_in[TH * TW];   // input tile with halo
    __shared__ float s_v[TY * TW];    // after vertical pass
    __shared__ float s_red[32];

    int tid = threadIdx.x;
    int n   = blockIdx.z;
    int ty0 = blockIdx.y * TY;
    int tx0 = blockIdx.x * TX;
    const float* img = src + (long)n * Hd * Wd;

    // Load halo tile (zeros out-of-bounds)
    for (int item = tid; item < TH * TW; item += 1024) {
        int ly = item / TW, lx = item - ly * TW;
        int gy = ty0 + ly - RAD, gx = tx0 + lx - RAD;
        float v = 0.f;
        if (gy >= 0 && gy < Hd && gx >= 0 && gx < Wd)
            v = img[(long)gy * Wd + gx];
        s_in[item] = v;
    }
    __syncthreads();

    // Vertical 15-tap: TY x TW outputs
    for (int item = tid; item < TY * TW; item += 1024) {
        int vy = item / TW, vx = item - vy * TW;
        float s = 0.f;
        #pragma unroll
        for (int d = 0; d < KS; ++d) s += s_in[(vy + d) * TW + vx];
        s_v[item] = s;
    }
    __syncthreads();

    // Horizontal 15-tap + square: one output per thread
    int ty = tid >> 5, tx = tid & 31;
    float s = 0.f;
    #pragma unroll
    for (int d = 0; d < KS; ++d) s += s_v[ty * TW + tx + d];
    float sq = s * s;

    // Block reduce
    #pragma unroll
    for (int off = 16; off > 0; off >>= 1)
        sq += __shfl_down_sync(0xFFFFFFFFu, sq, off);
    if ((tid & 31) == 0) s_red[tid >> 5] = sq;
    __syncthreads();
    if (tid < 32) {
        float v = s_red[tid];
        #pragma unroll
        for (int off = 16; off > 0; off >>= 1)
            v += __shfl_down_sync(0xFFFFFFFFu, v, off);
        if (tid == 0) atomicAdd(&g_acc[accIdx], (double)v);
    }
}

__global__ void k_finalize(float* out) {
    double y = g_acc[0] / (double)((long)NB * HH * WW);
    double u = g_acc[1] / (double)((long)NB * HQ * WQ);
    double v = g_acc[2] / (double)((long)NB * HQ * WQ);
    out[0] = (float)(y + u + v);
}

extern "C" void kernel_launch(void* const* d_in, const int* in_sizes, int n_in,
                              void* d_out, int out_size) {
    const float* in = (const float*)d_in[0];
    const float* tg = (const float*)d_in[1];
    float* out = (float*)d_out;
    (void)in_sizes; (void)n_in; (void)out_size;

    k_zero<<<1, 32>>>();
    k_diff<<<(NB * HQ * WQ) / 256, 256>>>(in, tg);

    float* yd; cudaGetSymbolAddress((void**)&yd, g_yd);
    float* ud; cudaGetSymbolAddress((void**)&ud, g_ud);
    float* vd; cudaGetSymbolAddress((void**)&vd, g_vd);

    dim3 gy(WW / TX, HH / TY, NB);   // 16x16x16
    dim3 gc(WQ / TX, HQ / TY, NB);   // 8x8x16
    k_filter<<<gy, 1024>>>(yd, HH, WW, 0);
    k_filter<<<gc, 1024>>>(ud, HQ, WQ, 1);
    k_filter<<<gc, 1024>>>(vd, HQ, WQ, 2);

    k_finalize<<<1, 1>>>(out);
}

// round 2
// speedup vs baseline: 1.2785x; 1.2785x over previous
#include <cuda_runtime.h>

#define NB 16
#define HH 512
#define WW 512
#define HQ 256
#define WQ 256
#define RAD 7

// Scratch (device globals; allocation in kernel_launch is forbidden)
__device__ float  g_yd[NB * HH * WW];   // Y diff
__device__ float  g_ud[NB * HQ * WQ];   // U diff
__device__ float  g_vd[NB * HQ * WQ];   // V diff
__device__ float  g_yv[NB * HH * WW];   // vertically filtered Y
__device__ float  g_uv[NB * HQ * WQ];   // vertically filtered U
__device__ float  g_vv[NB * HQ * WQ];   // vertically filtered V
__device__ double g_acc[2];             // [0]=Y sumsq, [1]=U+V sumsq

__global__ void k_zero() {
    if (threadIdx.x < 2) g_acc[threadIdx.x] = 0.0;
}

// ---------------------------------------------------------------------------
// k_diff: YUV420 channels of (input - target). Thread = 2 rows x 4 cols.
// ---------------------------------------------------------------------------
__global__ void k_diff(const float* __restrict__ in, const float* __restrict__ tg) {
    int idx = blockIdx.x * blockDim.x + threadIdx.x;   // over NB*HQ*(WQ/2)
    if (idx >= NB * HQ * (WQ / 2)) return;
    int wq4 = idx & 127;            // 4-col group (WW/4 = 128)
    int hq  = (idx >> 7) & 255;
    int n   = idx >> 15;

    const long plane = (long)HH * WW;
    long base = (long)n * 3 * plane + (long)(2 * hq) * WW + 4 * wq4;

    const float4* i4 = (const float4*)in;
    const float4* t4 = (const float4*)tg;
    long b4 = base >> 2;
    long p4 = plane >> 2;
    long w4 = WW >> 2;

    float4 dr0, dg0, db0, dr1, dg1, db1;
    {
        float4 a = i4[b4],          b = t4[b4];
        dr0 = make_float4(a.x-b.x, a.y-b.y, a.z-b.z, a.w-b.w);
        a = i4[b4 + p4];            b = t4[b4 + p4];
        dg0 = make_float4(a.x-b.x, a.y-b.y, a.z-b.z, a.w-b.w);
        a = i4[b4 + 2*p4];          b = t4[b4 + 2*p4];
        db0 = make_float4(a.x-b.x, a.y-b.y, a.z-b.z, a.w-b.w);
        a = i4[b4 + w4];            b = t4[b4 + w4];
        dr1 = make_float4(a.x-b.x, a.y-b.y, a.z-b.z, a.w-b.w);
        a = i4[b4 + w4 + p4];       b = t4[b4 + w4 + p4];
        dg1 = make_float4(a.x-b.x, a.y-b.y, a.z-b.z, a.w-b.w);
        a = i4[b4 + w4 + 2*p4];     b = t4[b4 + w4 + 2*p4];
        db1 = make_float4(a.x-b.x, a.y-b.y, a.z-b.z, a.w-b.w);
    }

    float4 y0 = make_float4(0.299f*dr0.x + 0.587f*dg0.x + 0.114f*db0.x,
                            0.299f*dr0.y + 0.587f*dg0.y + 0.114f*db0.y,
                            0.299f*dr0.z + 0.587f*dg0.z + 0.114f*db0.z,
                            0.299f*dr0.w + 0.587f*dg0.w + 0.114f*db0.w);
    float4 y1 = make_float4(0.299f*dr1.x + 0.587f*dg1.x + 0.114f*db1.x,
                            0.299f*dr1.y + 0.587f*dg1.y + 0.114f*db1.y,
                            0.299f*dr1.z + 0.587f*dg1.z + 0.114f*db1.z,
                            0.299f*dr1.w + 0.587f*dg1.w + 0.114f*db1.w);

    // 2x2 sums for the two chroma pixels this thread covers
    float drA = dr0.x + dr0.y + dr1.x + dr1.y;
    float dgA = dg0.x + dg0.y + dg1.x + dg1.y;
    float dbA = db0.x + db0.y + db1.x + db1.y;
    float drB = dr0.z + dr0.w + dr1.z + dr1.w;
    float dgB = dg0.z + dg0.w + dg1.z + dg1.w;
    float dbB = db0.z + db0.w + db1.z + db1.w;

    float2 u = make_float2(0.25f * (-0.169f*drA - 0.331f*dgA + 0.5f*dbA),
                           0.25f * (-0.169f*drB - 0.331f*dgB + 0.5f*dbB));
    float2 v = make_float2(0.25f * ( 0.5f*drA - 0.46f*dgA - 0.04f*dbA),
                           0.25f * ( 0.5f*drB - 0.46f*dgB - 0.04f*dbB));

    long ybase4 = ((long)n * plane + (long)(2 * hq) * WW + 4 * wq4) >> 2;
    ((float4*)g_yd)[ybase4]      = y0;
    ((float4*)g_yd)[ybase4 + w4] = y1;

    long cbase = ((long)n * HQ + hq) * WQ + 2 * wq4;
    *(float2*)(g_ud + cbase) = u;
    *(float2*)(g_vd + cbase) = v;
}

// ---------------------------------------------------------------------------
// k_passV: vertical 15-tap box (zero-pad SAME) via register sliding window.
// grid (8, 48), block 128. z<16: Y image z; 16..31: U; 32..47: V.
// ---------------------------------------------------------------------------
__global__ void __launch_bounds__(128)
k_passV() {
    int gy = blockIdx.x;
    int z  = blockIdx.y;
    int t  = threadIdx.x;

    const float* src; float* dst; int H, W;
    if (z < 16)      { H = HH; W = WW; src = g_yd + (long)z * HH * WW;        dst = g_yv + (long)z * HH * WW; }
    else if (z < 32) { H = HQ; W = WQ; src = g_ud + (long)(z - 16) * HQ * WQ; dst = g_uv + (long)(z - 16) * HQ * WQ; }
    else             { H = HQ; W = WQ; src = g_vd + (long)(z - 32) * HQ * WQ; dst = g_vv + (long)(z - 32) * HQ * WQ; }

    int W4 = W >> 2;
    if (t >= W4) return;
    int R  = H >> 3;          // 8 row-groups in both cases
    int y0 = gy * R;

    const float4* s4 = (const float4*)src;
    float4* d4 = (float4*)dst;

    float4 sum = make_float4(0.f, 0.f, 0.f, 0.f);
    #pragma unroll
    for (int d = -RAD; d <= RAD; ++d) {
        int yy = y0 + d;
        if (yy >= 0 && yy < H) {
            float4 v = s4[(long)yy * W4 + t];
            sum.x += v.x; sum.y += v.y; sum.z += v.z; sum.w += v.w;
        }
    }
    for (int y = y0; y < y0 + R; ++y) {
        d4[(long)y * W4 + t] = sum;
        int ya = y + RAD + 1, yr = y - RAD;
        if (ya < H) {
            float4 v = s4[(long)ya * W4 + t];
            sum.x += v.x; sum.y += v.y; sum.z += v.z; sum.w += v.w;
        }
        if (yr >= 0) {
            float4 v = s4[(long)yr * W4 + t];
            sum.x -= v.x; sum.y -= v.y; sum.z -= v.z; sum.w -= v.w;
        }
    }
}

// ---------------------------------------------------------------------------
// k_passH: horizontal 15-tap box via per-warp row prefix sums, fused square +
// reduce. grid 256, block 256 (8 warps). Blocks 0..127: Y rows; 128..255: U/V.
// ---------------------------------------------------------------------------
__global__ void __launch_bounds__(256)
k_passH() {
    __shared__ float buf[8][WW + 16];   // per-warp row prefix buffer (max W=512)
    __shared__ double red[8];

    const unsigned FULL = 0xFFFFFFFFu;
    int warp = threadIdx.x >> 5;
    int lane = threadIdx.x & 31;
    int bid  = blockIdx.x;
    bool isY = bid < 128;
    int W      = isY ? WW : WQ;
    int chunks = W >> 7;               // 128 elements per chunk

    float* B = buf[warp];
    if (lane < 8) B[lane] = 0.f;       // front pad: P[x-8..x-1] = 0
    __syncwarp();

    int gw = isY ? bid * 8 + warp : (bid - 128) * 8 + warp;  // 0..1023
    double dacc = 0.0;

    for (int r = 0; r < 8; ++r) {
        int row = gw * 8 + r;          // 0..8191
        const float* src;
        if (isY) src = g_yv + (long)row * WW;
        else if (row < 4096) src = g_uv + (long)row * WQ;
        else                 src = g_vv + (long)(row - 4096) * WQ;

        // inclusive prefix of the row into B[8..8+W)
        float carry = 0.f;
        for (int c = 0; c < chunks; ++c) {
            float4 v = ((const float4*)src)[c * 32 + lane];
            float p1 = v.x + v.y, p2 = p1 + v.z, p3 = p2 + v.w;
            float tt = p3;
            #pragma unroll
            for (int off = 1; off < 32; off <<= 1) {
                float o = __shfl_up_sync(FULL, tt, off);
                if (lane >= off) tt += o;
            }
            float base = tt - p3 + carry;
            ((float4*)(B + 8))[c * 32 + lane] =
                make_float4(base + v.x, base + p1, base + p2, base + p3);
            carry += __shfl_sync(FULL, tt, 31);
        }
        __syncwarp();
        if (lane < 7) B[8 + W + lane] = carry;   // high pad: clamp to total
        __syncwarp();

        // out[x] = P[x+7] - P[x-8] = B[x+15] - B[x]
        float racc = 0.f;
        for (int c = 0; c < chunks; ++c) {
            int x = c * 128 + 4 * lane;
            float4 b = ((const float4*)B)[x >> 2];
            float o0 = B[x + 15] - b.x;
            float o1 = B[x + 16] - b.y;
            float o2 = B[x + 17] - b.z;
            float o3 = B[x + 18] - b.w;
            racc += o0*o0 + o1*o1 + o2*o2 + o3*o3;
        }
        dacc += (double)racc;
        __syncwarp();
    }

    // warp reduce then block reduce
    #pragma unroll
    for (int off = 16; off > 0; off >>= 1)
        dacc += __shfl_down_sync(FULL, dacc, off);
    if (lane == 0) red[warp] = dacc;
    __syncthreads();
    if (threadIdx.x == 0) {
        double s = 0.0;
        #pragma unroll
        for (int w = 0; w < 8; ++w) s += red[w];
        atomicAdd(&g_acc[isY ? 0 : 1], s);
    }
}

__global__ void k_finalize(float* out) {
    double y = g_acc[0] / (double)((long)NB * HH * WW);
    double c = g_acc[1] / (double)((long)NB * HQ * WQ);
    out[0] = (float)(y + c);
}

extern "C" void kernel_launch(void* const* d_in, const int* in_sizes, int n_in,
                              void* d_out, int out_size) {
    const float* in = (const float*)d_in[0];
    const float* tg = (const float*)d_in[1];
    float* out = (float*)d_out;
    (void)in_sizes; (void)n_in; (void)out_size;

    k_zero<<<1, 32>>>();
    k_diff<<<(NB * HQ * (WQ / 2)) / 256, 256>>>(in, tg);
    k_passV<<<dim3(8, 48), 128>>>();
    k_passH<<<256, 256>>>();
    k_finalize<<<1, 1>>>(out);
}

// round 3
// speedup vs baseline: 1.8172x; 1.4214x over previous
#include <cuda_runtime.h>

#define NB 16
#define HH 512
#define WW 512
#define HQ 256
#define WQ 256
#define RAD 7

// Scratch (device globals; allocation in kernel_launch is forbidden)
__device__ float  g_yd[NB * HH * WW];        // Y diff
__device__ float  g_cd[2 * NB * HQ * WQ];    // chroma diff: planes 0..15 = U, 16..31 = V
__device__ float  g_yv[NB * HH * WW];        // vertically filtered Y
__device__ float  g_cv[2 * NB * HQ * WQ];    // vertically filtered chroma
__device__ double g_acc[2];                  // [0]=Y sumsq, [1]=U+V sumsq
__device__ unsigned int g_done;              // block-completion counter (self-resetting)

// ---------------------------------------------------------------------------
// k_diff: YUV420 channels of (input - target). Thread = 2 rows x 4 cols.
// Block 0 also zeroes the accumulators (safe: passH runs after this kernel).
// ---------------------------------------------------------------------------
__global__ void k_diff(const float* __restrict__ in, const float* __restrict__ tg) {
    int idx = blockIdx.x * blockDim.x + threadIdx.x;   // over NB*HQ*(WQ/2)
    if (idx < 2) g_acc[idx] = 0.0;
    if (idx >= NB * HQ * (WQ / 2)) return;
    int wq4 = idx & 127;            // 4-col group (WW/4 = 128)
    int hq  = (idx >> 7) & 255;
    int n   = idx >> 15;

    const long plane = (long)HH * WW;
    long base = (long)n * 3 * plane + (long)(2 * hq) * WW + 4 * wq4;

    const float4* i4 = (const float4*)in;
    const float4* t4 = (const float4*)tg;
    long b4 = base >> 2;
    long p4 = plane >> 2;
    long w4 = WW >> 2;

    float4 dr0, dg0, db0, dr1, dg1, db1;
    {
        float4 a = i4[b4],          b = t4[b4];
        dr0 = make_float4(a.x-b.x, a.y-b.y, a.z-b.z, a.w-b.w);
        a = i4[b4 + p4];            b = t4[b4 + p4];
        dg0 = make_float4(a.x-b.x, a.y-b.y, a.z-b.z, a.w-b.w);
        a = i4[b4 + 2*p4];          b = t4[b4 + 2*p4];
        db0 = make_float4(a.x-b.x, a.y-b.y, a.z-b.z, a.w-b.w);
        a = i4[b4 + w4];            b = t4[b4 + w4];
        dr1 = make_float4(a.x-b.x, a.y-b.y, a.z-b.z, a.w-b.w);
        a = i4[b4 + w4 + p4];       b = t4[b4 + w4 + p4];
        dg1 = make_float4(a.x-b.x, a.y-b.y, a.z-b.z, a.w-b.w);
        a = i4[b4 + w4 + 2*p4];     b = t4[b4 + w4 + 2*p4];
        db1 = make_float4(a.x-b.x, a.y-b.y, a.z-b.z, a.w-b.w);
    }

    float4 y0 = make_float4(0.299f*dr0.x + 0.587f*dg0.x + 0.114f*db0.x,
                            0.299f*dr0.y + 0.587f*dg0.y + 0.114f*db0.y,
                            0.299f*dr0.z + 0.587f*dg0.z + 0.114f*db0.z,
                            0.299f*dr0.w + 0.587f*dg0.w + 0.114f*db0.w);
    float4 y1 = make_float4(0.299f*dr1.x + 0.587f*dg1.x + 0.114f*db1.x,
                            0.299f*dr1.y + 0.587f*dg1.y + 0.114f*db1.y,
                            0.299f*dr1.z + 0.587f*dg1.z + 0.114f*db1.z,
                            0.299f*dr1.w + 0.587f*dg1.w + 0.114f*db1.w);

    float drA = dr0.x + dr0.y + dr1.x + dr1.y;
    float dgA = dg0.x + dg0.y + dg1.x + dg1.y;
    float dbA = db0.x + db0.y + db1.x + db1.y;
    float drB = dr0.z + dr0.w + dr1.z + dr1.w;
    float dgB = dg0.z + dg0.w + dg1.z + dg1.w;
    float dbB = db0.z + db0.w + db1.z + db1.w;

    float2 u = make_float2(0.25f * (-0.169f*drA - 0.331f*dgA + 0.5f*dbA),
                           0.25f * (-0.169f*drB - 0.331f*dgB + 0.5f*dbB));
    float2 v = make_float2(0.25f * ( 0.5f*drA - 0.46f*dgA - 0.04f*dbA),
                           0.25f * ( 0.5f*drB - 0.46f*dgB - 0.04f*dbB));

    long ybase4 = ((long)n * plane + (long)(2 * hq) * WW + 4 * wq4) >> 2;
    ((float4*)g_yd)[ybase4]      = y0;
    ((float4*)g_yd)[ybase4 + w4] = y1;

    long cbase = ((long)n * HQ + hq) * WQ + 2 * wq4;           // U plane n
    *(float2*)(g_cd + cbase) = u;
    *(float2*)(g_cd + (long)NB * HQ * WQ + cbase) = v;         // V plane NB+n
}

// ---------------------------------------------------------------------------
// k_passV: vertical 15-tap box (zero-pad SAME), register sliding window.
// grid (32, 48), block 128. z<16: Y image z (R=16); else chroma plane z-16 (R=8).
// ---------------------------------------------------------------------------
__global__ void __launch_bounds__(128)
k_passV() {
    int gy = blockIdx.x;
    int z  = blockIdx.y;
    int t  = threadIdx.x;

    const float* src; float* dst; int H, W4;
    if (z < 16) {
        H = HH; W4 = WW >> 2;
        src = g_yd + (long)z * HH * WW;
        dst = g_yv + (long)z * HH * WW;
    } else {
        H = HQ; W4 = WQ >> 2;
        src = g_cd + (long)(z - 16) * HQ * WQ;
        dst = g_cv + (long)(z - 16) * HQ * WQ;
    }
    if (t >= W4) return;
    int R  = H >> 5;          // 32 row-groups: Y 16 rows, chroma 8 rows
    int y0 = gy * R;

    const float4* s4 = (const float4*)src;
    float4* d4 = (float4*)dst;

    float4 sum = make_float4(0.f, 0.f, 0.f, 0.f);
    #pragma unroll
    for (int d = -RAD; d <= RAD; ++d) {
        int yy = y0 + d;
        if (yy >= 0 && yy < H) {
            float4 v = s4[(long)yy * W4 + t];
            sum.x += v.x; sum.y += v.y; sum.z += v.z; sum.w += v.w;
        }
    }
    for (int y = y0; y < y0 + R; ++y) {
        d4[(long)y * W4 + t] = sum;
        int ya = y + RAD + 1, yr = y - RAD;
        if (ya < H) {
            float4 v = s4[(long)ya * W4 + t];
            sum.x += v.x; sum.y += v.y; sum.z += v.z; sum.w += v.w;
        }
        if (yr >= 0) {
            float4 v = s4[(long)yr * W4 + t];
            sum.x -= v.x; sum.y -= v.y; sum.z -= v.z; sum.w -= v.w;
        }
    }
}

// ---------------------------------------------------------------------------
// k_passH: horizontal 15-tap box via per-warp row prefix sums, fused square +
// reduce + finalize. One warp per row. grid 2048, block 256 (8 warps).
// Blocks 0..1023: Y rows (8192 x 512). Blocks 1024..2047: chroma (8192 x 256).
// ---------------------------------------------------------------------------
#define NBLK_H 2048
__global__ void __launch_bounds__(256)
k_passH(float* __restrict__ out) {
    __shared__ float buf[8][WW + 16];
    __shared__ double red[8];

    const unsigned FULL = 0xFFFFFFFFu;
    int warp = threadIdx.x >> 5;
    int lane = threadIdx.x & 31;
    int bid  = blockIdx.x;
    bool isY = bid < 1024;
    int W      = isY ? WW : WQ;
    int chunks = W >> 7;               // 128 elements per chunk

    float* B = buf[warp];
    if (lane < 8) B[lane] = 0.f;       // front pad: P[x-8..x-1] = 0

    int row = (isY ? bid : bid - 1024) * 8 + warp;   // 0..8191
    const float* src = isY ? g_yv + (long)row * WW
                           : g_cv + (long)row * WQ;

    // inclusive prefix of the row into B[8..8+W)
    float carry = 0.f;
    for (int c = 0; c < chunks; ++c) {
        float4 v = ((const float4*)src)[c * 32 + lane];
        float p1 = v.x + v.y, p2 = p1 + v.z, p3 = p2 + v.w;
        float tt = p3;
        #pragma unroll
        for (int off = 1; off < 32; off <<= 1) {
            float o = __shfl_up_sync(FULL, tt, off);
            if (lane >= off) tt += o;
        }
        float base = tt - p3 + carry;
        ((float4*)(B + 8))[c * 32 + lane] =
            make_float4(base + v.x, base + p1, base + p2, base + p3);
        carry += __shfl_sync(FULL, tt, 31);
    }
    __syncwarp();
    if (lane < 7) B[8 + W + lane] = carry;   // high pad: clamp to total
    __syncwarp();

    // out[x] = P[x+7] - P[x-8] = B[x+15] - B[x]; square + accumulate
    float racc = 0.f;
    for (int c = 0; c < chunks; ++c) {
        int x = c * 128 + 4 * lane;
        float4 b = ((const float4*)B)[x >> 2];
        float o0 = B[x + 15] - b.x;
        float o1 = B[x + 16] - b.y;
        float o2 = B[x + 17] - b.z;
        float o3 = B[x + 18] - b.w;
        racc += o0*o0 + o1*o1 + o2*o2 + o3*o3;
    }
    double dacc = (double)racc;

    // warp reduce, then block reduce, then one atomic per block
    #pragma unroll
    for (int off = 16; off > 0; off >>= 1)
        dacc += __shfl_down_sync(FULL, dacc, off);
    if (lane == 0) red[warp] = dacc;
    __syncthreads();
    if (threadIdx.x == 0) {
        double s = 0.0;
        #pragma unroll
        for (int w = 0; w < 8; ++w) s += red[w];
        atomicAdd(&g_acc[isY ? 0 : 1], s);
        __threadfence();
        unsigned int prev = atomicAdd(&g_done, 1u);
        if (prev == NBLK_H - 1) {
            // last block: finalize and reset counter for next graph replay
            volatile double* acc = g_acc;
            double y = acc[0] / (double)((long)NB * HH * WW);
            double c = acc[1] / (double)((long)NB * HQ * WQ);
            out[0] = (float)(y + c);
            g_done = 0u;
        }
    }
}

extern "C" void kernel_launch(void* const* d_in, const int* in_sizes, int n_in,
                              void* d_out, int out_size) {
    const float* in = (const float*)d_in[0];
    const float* tg = (const float*)d_in[1];
    float* out = (float*)d_out;
    (void)in_sizes; (void)n_in; (void)out_size;

    k_diff<<<(NB * HQ * (WQ / 2)) / 256, 256>>>(in, tg);
    k_passV<<<dim3(32, 48), 128>>>();
    k_passH<<<NBLK_H, 256>>>(out);
}

// round 4
// speedup vs baseline: 2.0800x; 1.1446x over previous
#include <cuda_runtime.h>

#define NB 16
#define HH 512
#define WW 512
#define HQ 256
#define WQ 256
#define RAD 7

// Scratch (device globals; allocation in kernel_launch is forbidden)
__device__ float  g_yh[NB * HH * WW];        // horizontally filtered Y diff
__device__ float  g_ch[2 * NB * HQ * WQ];    // horizontally filtered chroma (U planes 0..15, V planes 16..31)
__device__ double g_acc[2];                  // [0]=Y sumsq, [1]=U+V sumsq
__device__ unsigned int g_done;              // completion counter (self-resetting)

// ---------------------------------------------------------------------------
// k_diff_h: YUV420 diff channels + horizontal 15-tap box filter, fused.
// One warp = one Y row-pair (2x512 pixels of both images) = one chroma row.
// grid 512, block 256 (8 warps). Scan via warp prefix sums in smem.
// ---------------------------------------------------------------------------
__global__ void __launch_bounds__(256)
k_diff_h(const float* __restrict__ in, const float* __restrict__ tg) {
    __shared__ float sP[8][WW + 16];    // per-warp prefix buffer
    __shared__ float sC[8][2 * WQ];     // per-warp raw chroma rows (U|V)

    const unsigned FULL = 0xFFFFFFFFu;
    int warp = threadIdx.x >> 5;
    int lane = threadIdx.x & 31;

    if (blockIdx.x == 0 && threadIdx.x < 2) g_acc[threadIdx.x] = 0.0;

    int gw = blockIdx.x * 8 + warp;     // 0..4095 row-pairs
    int n  = gw >> 8;                   // image
    int hq = gw & 255;                  // chroma row / y row-pair

    const long plane = (long)HH * WW;
    const long p4 = plane >> 2, w4 = WW >> 2;
    long base4 = ((long)n * 3 * plane + (long)(2 * hq) * WW) >> 2;

    const float4* i4 = (const float4*)in;
    const float4* t4 = (const float4*)tg;

    float* U = sC[warp];
    float* V = sC[warp] + WQ;
    float* P = sP[warp];

    float4 yd0[4], yd1[4];

    #pragma unroll
    for (int c = 0; c < 4; ++c) {
        long o = base4 + c * 32 + lane;
        float4 a, b, dr0, dg0, db0, dr1, dg1, db1;
        a = i4[o];            b = t4[o];
        dr0 = make_float4(a.x-b.x, a.y-b.y, a.z-b.z, a.w-b.w);
        a = i4[o + p4];       b = t4[o + p4];
        dg0 = make_float4(a.x-b.x, a.y-b.y, a.z-b.z, a.w-b.w);
        a = i4[o + 2*p4];     b = t4[o + 2*p4];
        db0 = make_float4(a.x-b.x, a.y-b.y, a.z-b.z, a.w-b.w);
        a = i4[o + w4];       b = t4[o + w4];
        dr1 = make_float4(a.x-b.x, a.y-b.y, a.z-b.z, a.w-b.w);
        a = i4[o + w4 + p4];  b = t4[o + w4 + p4];
        dg1 = make_float4(a.x-b.x, a.y-b.y, a.z-b.z, a.w-b.w);
        a = i4[o + w4 + 2*p4];b = t4[o + w4 + 2*p4];
        db1 = make_float4(a.x-b.x, a.y-b.y, a.z-b.z, a.w-b.w);

        yd0[c] = make_float4(0.299f*dr0.x + 0.587f*dg0.x + 0.114f*db0.x,
                             0.299f*dr0.y + 0.587f*dg0.y + 0.114f*db0.y,
                             0.299f*dr0.z + 0.587f*dg0.z + 0.114f*db0.z,
                             0.299f*dr0.w + 0.587f*dg0.w + 0.114f*db0.w);
        yd1[c] = make_float4(0.299f*dr1.x + 0.587f*dg1.x + 0.114f*db1.x,
                             0.299f*dr1.y + 0.587f*dg1.y + 0.114f*db1.y,
                             0.299f*dr1.z + 0.587f*dg1.z + 0.114f*db1.z,
                             0.299f*dr1.w + 0.587f*dg1.w + 0.114f*db1.w);

        float drA = dr0.x + dr0.y + dr1.x + dr1.y;
        float dgA = dg0.x + dg0.y + dg1.x + dg1.y;
        float dbA = db0.x + db0.y + db1.x + db1.y;
        float drB = dr0.z + dr0.w + dr1.z + dr1.w;
        float dgB = dg0.z + dg0.w + dg1.z + dg1.w;
        float dbB = db0.z + db0.w + db1.z + db1.w;

        *(float2*)(U + c*64 + 2*lane) =
            make_float2(0.25f * (-0.169f*drA - 0.331f*dgA + 0.5f*dbA),
                        0.25f * (-0.169f*drB - 0.331f*dgB + 0.5f*dbB));
        *(float2*)(V + c*64 + 2*lane) =
            make_float2(0.25f * ( 0.5f*drA - 0.46f*dgA - 0.04f*dbA),
                        0.25f * ( 0.5f*drB - 0.46f*dgB - 0.04f*dbB));
    }
    __syncwarp();

    // ---- horizontal box filter of one row via prefix sum, emit to dst ----
    // Y rows from registers
    #pragma unroll
    for (int r = 0; r < 2; ++r) {
        float4* Y = r ? yd1 : yd0;
        if (lane < 8) P[lane] = 0.f;
        float carry = 0.f;
        #pragma unroll
        for (int c = 0; c < 4; ++c) {
            float4 v = Y[c];
            float p1 = v.x + v.y, p2 = p1 + v.z, p3 = p2 + v.w;
            float tt = p3;
            #pragma unroll
            for (int off = 1; off < 32; off <<= 1) {
                float o = __shfl_up_sync(FULL, tt, off);
                if (lane >= off) tt += o;
            }
            float bb = tt - p3 + carry;
            ((float4*)(P + 8))[c * 32 + lane] =
                make_float4(bb + v.x, bb + p1, bb + p2, bb + p3);
            carry += __shfl_sync(FULL, tt, 31);
        }
        __syncwarp();
        if (lane < 7) P[8 + WW + lane] = carry;
        __syncwarp();
        float4* dst = (float4*)(g_yh + (long)n * plane + (long)(2*hq + r) * WW);
        #pragma unroll
        for (int c = 0; c < 4; ++c) {
            int x = c * 128 + 4 * lane;
            float4 b = ((const float4*)P)[x >> 2];
            dst[x >> 2] = make_float4(P[x + 15] - b.x, P[x + 16] - b.y,
                                      P[x + 17] - b.z, P[x + 18] - b.w);
        }
        __syncwarp();
    }

    // Chroma rows from smem staging
    #pragma unroll
    for (int r = 0; r < 2; ++r) {
        const float* R = r ? V : U;
        if (lane < 8) P[lane] = 0.f;
        float carry = 0.f;
        #pragma unroll
        for (int c = 0; c < 2; ++c) {
            float4 v = ((const float4*)R)[c * 32 + lane];
            float p1 = v.x + v.y, p2 = p1 + v.z, p3 = p2 + v.w;
            float tt = p3;
            #pragma unroll
            for (int off = 1; off < 32; off <<= 1) {
                float o = __shfl_up_sync(FULL, tt, off);
                if (lane >= off) tt += o;
            }
            float bb = tt - p3 + carry;
            ((float4*)(P + 8))[c * 32 + lane] =
                make_float4(bb + v.x, bb + p1, bb + p2, bb + p3);
            carry += __shfl_sync(FULL, tt, 31);
        }
        __syncwarp();
        if (lane < 7) P[8 + WQ + lane] = carry;
        __syncwarp();
        float4* dst = (float4*)(g_ch + ((long)(r * NB + n) * HQ + hq) * WQ);
        #pragma unroll
        for (int c = 0; c < 2; ++c) {
            int x = c * 128 + 4 * lane;
            float4 b = ((const float4*)P)[x >> 2];
            dst[x >> 2] = make_float4(P[x + 15] - b.x, P[x + 16] - b.y,
                                      P[x + 17] - b.z, P[x + 18] - b.w);
        }
        __syncwarp();
    }
}

// ---------------------------------------------------------------------------
// k_v: vertical 15-tap box (zero-pad SAME) via register sliding window,
// fused square + global reduce + finalize. No stores except accumulators.
// grid 192, block 256. Blocks 0..127: Y (thread = 4 cols x 32 rows).
// Blocks 128..191: chroma planes.
// ---------------------------------------------------------------------------
#define NBLK_V 192
#define RGRP 32
__global__ void __launch_bounds__(256)
k_v(float* __restrict__ out) {
    __shared__ double red[8];
    const unsigned FULL = 0xFFFFFFFFu;

    int t = blockIdx.x * 256 + threadIdx.x;
    bool isY = t < 32768;

    const float* src; int H, W4, y0;
    if (isY) {
        int colg = t & 127, rowg = (t >> 7) & 15, n = t >> 11;
        H = HH; W4 = WW >> 2; y0 = rowg * RGRP;
        src = g_yh + (long)n * HH * WW + 4 * colg;
    } else {
        int t2 = t - 32768;
        int colg = t2 & 63, rowg = (t2 >> 6) & 7, pl = t2 >> 9;  // 0..31
        H = HQ; W4 = WQ >> 2; y0 = rowg * RGRP;
        src = g_ch + (long)pl * HQ * WQ + 4 * colg;
    }

    float4 sum = make_float4(0.f, 0.f, 0.f, 0.f);
    #pragma unroll
    for (int d = -RAD; d <= RAD; ++d) {
        int yy = y0 + d;
        if (yy >= 0 && yy < H) {
            float4 v = *(const float4*)(src + (long)yy * 4 * W4);
            sum.x += v.x; sum.y += v.y; sum.z += v.z; sum.w += v.w;
        }
    }
    float racc = 0.f;
    #pragma unroll 4
    for (int y = y0; y < y0 + RGRP; ++y) {
        racc += sum.x*sum.x + sum.y*sum.y + sum.z*sum.z + sum.w*sum.w;
        int ya = y + RAD + 1, yr = y - RAD;
        if (ya < H) {
            float4 v = *(const float4*)(src + (long)ya * 4 * W4);
            sum.x += v.x; sum.y += v.y; sum.z += v.z; sum.w += v.w;
        }
        if (yr >= 0) {
            float4 v = *(const float4*)(src + (long)yr * 4 * W4);
            sum.x -= v.x; sum.y -= v.y; sum.z -= v.z; sum.w -= v.w;
        }
    }
    double dacc = (double)racc;

    #pragma unroll
    for (int off = 16; off > 0; off >>= 1)
        dacc += __shfl_down_sync(FULL, dacc, off);
    int warp = threadIdx.x >> 5, lane = threadIdx.x & 31;
    if (lane == 0) red[warp] = dacc;
    __syncthreads();
    if (threadIdx.x == 0) {
        double s = 0.0;
        #pragma unroll
        for (int w = 0; w < 8; ++w) s += red[w];
        atomicAdd(&g_acc[isY ? 0 : 1], s);
        __threadfence();
        unsigned int prev = atomicAdd(&g_done, 1u);
        if (prev == NBLK_V - 1) {
            volatile double* acc = g_acc;
            double y = acc[0] / (double)((long)NB * HH * WW);
            double c = acc[1] / (double)((long)NB * HQ * WQ);
            out[0] = (float)(y + c);
            g_done = 0u;
        }
    }
}

extern "C" void kernel_launch(void* const* d_in, const int* in_sizes, int n_in,
                              void* d_out, int out_size) {
    const float* in = (const float*)d_in[0];
    const float* tg = (const float*)d_in[1];
    float* out = (float*)d_out;
    (void)in_sizes; (void)n_in; (void)out_size;

    k_diff_h<<<512, 256>>>(in, tg);
    k_v<<<NBLK_V, 256>>>(out);
}

// round 5
// speedup vs baseline: 2.3151x; 1.1130x over previous
#include <cuda_runtime.h>

#define NB 16
#define HH 512
#define WW 512
#define HQ 256
#define WQ 256
#define RAD 7

// Scratch (device globals; allocation in kernel_launch is forbidden)
__device__ float  g_yh[NB * HH * WW];        // horizontally filtered Y diff
__device__ float  g_ch[2 * NB * HQ * WQ];    // horizontally filtered chroma (U planes 0..15, V planes 16..31)
__device__ double g_acc[2];                  // [0]=Y sumsq, [1]=U+V sumsq
__device__ unsigned int g_done;              // completion counter (self-resetting)

// ---------------------------------------------------------------------------
// k_diff_h: YUV420 diff channels + horizontal 15-tap box filter, fused.
// One warp = one Y row-pair (2x512 pixels of both images) = one chroma row.
// grid 512, block 256 (8 warps). Scan via warp prefix sums in smem.
// ---------------------------------------------------------------------------
__global__ void __launch_bounds__(256)
k_diff_h(const float* __restrict__ in, const float* __restrict__ tg) {
    __shared__ float sP[8][WW + 16];    // per-warp prefix buffer
    __shared__ float sC[8][2 * WQ];     // per-warp raw chroma rows (U|V)

    const unsigned FULL = 0xFFFFFFFFu;
    int warp = threadIdx.x >> 5;
    int lane = threadIdx.x & 31;

    if (blockIdx.x == 0 && threadIdx.x < 2) g_acc[threadIdx.x] = 0.0;

    int gw = blockIdx.x * 8 + warp;     // 0..4095 row-pairs
    int n  = gw >> 8;                   // image
    int hq = gw & 255;                  // chroma row / y row-pair

    const long plane = (long)HH * WW;
    const long p4 = plane >> 2, w4 = WW >> 2;
    long base4 = ((long)n * 3 * plane + (long)(2 * hq) * WW) >> 2;

    const float4* i4 = (const float4*)in;
    const float4* t4 = (const float4*)tg;

    float* U = sC[warp];
    float* V = sC[warp] + WQ;
    float* P = sP[warp];

    float4 yd0[4], yd1[4];

    #pragma unroll
    for (int c = 0; c < 4; ++c) {
        long o = base4 + c * 32 + lane;
        float4 a, b, dr0, dg0, db0, dr1, dg1, db1;
        a = i4[o];            b = t4[o];
        dr0 = make_float4(a.x-b.x, a.y-b.y, a.z-b.z, a.w-b.w);
        a = i4[o + p4];       b = t4[o + p4];
        dg0 = make_float4(a.x-b.x, a.y-b.y, a.z-b.z, a.w-b.w);
        a = i4[o + 2*p4];     b = t4[o + 2*p4];
        db0 = make_float4(a.x-b.x, a.y-b.y, a.z-b.z, a.w-b.w);
        a = i4[o + w4];       b = t4[o + w4];
        dr1 = make_float4(a.x-b.x, a.y-b.y, a.z-b.z, a.w-b.w);
        a = i4[o + w4 + p4];  b = t4[o + w4 + p4];
        dg1 = make_float4(a.x-b.x, a.y-b.y, a.z-b.z, a.w-b.w);
        a = i4[o + w4 + 2*p4];b = t4[o + w4 + 2*p4];
        db1 = make_float4(a.x-b.x, a.y-b.y, a.z-b.z, a.w-b.w);

        yd0[c] = make_float4(0.299f*dr0.x + 0.587f*dg0.x + 0.114f*db0.x,
                             0.299f*dr0.y + 0.587f*dg0.y + 0.114f*db0.y,
                             0.299f*dr0.z + 0.587f*dg0.z + 0.114f*db0.z,
                             0.299f*dr0.w + 0.587f*dg0.w + 0.114f*db0.w);
        yd1[c] = make_float4(0.299f*dr1.x + 0.587f*dg1.x + 0.114f*db1.x,
                             0.299f*dr1.y + 0.587f*dg1.y + 0.114f*db1.y,
                             0.299f*dr1.z + 0.587f*dg1.z + 0.114f*db1.z,
                             0.299f*dr1.w + 0.587f*dg1.w + 0.114f*db1.w);

        float drA = dr0.x + dr0.y + dr1.x + dr1.y;
        float dgA = dg0.x + dg0.y + dg1.x + dg1.y;
        float dbA = db0.x + db0.y + db1.x + db1.y;
        float drB = dr0.z + dr0.w + dr1.z + dr1.w;
        float dgB = dg0.z + dg0.w + dg1.z + dg1.w;
        float dbB = db0.z + db0.w + db1.z + db1.w;

        *(float2*)(U + c*64 + 2*lane) =
            make_float2(0.25f * (-0.169f*drA - 0.331f*dgA + 0.5f*dbA),
                        0.25f * (-0.169f*drB - 0.331f*dgB + 0.5f*dbB));
        *(float2*)(V + c*64 + 2*lane) =
            make_float2(0.25f * ( 0.5f*drA - 0.46f*dgA - 0.04f*dbA),
                        0.25f * ( 0.5f*drB - 0.46f*dgB - 0.04f*dbB));
    }
    __syncwarp();

    // ---- horizontal box filter of one row via prefix sum, emit to dst ----
    // Y rows from registers
    #pragma unroll
    for (int r = 0; r < 2; ++r) {
        float4* Y = r ? yd1 : yd0;
        if (lane < 8) P[lane] = 0.f;
        float carry = 0.f;
        #pragma unroll
        for (int c = 0; c < 4; ++c) {
            float4 v = Y[c];
            float p1 = v.x + v.y, p2 = p1 + v.z, p3 = p2 + v.w;
            float tt = p3;
            #pragma unroll
            for (int off = 1; off < 32; off <<= 1) {
                float o = __shfl_up_sync(FULL, tt, off);
                if (lane >= off) tt += o;
            }
            float bb = tt - p3 + carry;
            ((float4*)(P + 8))[c * 32 + lane] =
                make_float4(bb + v.x, bb + p1, bb + p2, bb + p3);
            carry += __shfl_sync(FULL, tt, 31);
        }
        __syncwarp();
        if (lane < 7) P[8 + WW + lane] = carry;
        __syncwarp();
        float4* dst = (float4*)(g_yh + (long)n * plane + (long)(2*hq + r) * WW);
        #pragma unroll
        for (int c = 0; c < 4; ++c) {
            int x = c * 128 + 4 * lane;
            float4 b = ((const float4*)P)[x >> 2];
            dst[x >> 2] = make_float4(P[x + 15] - b.x, P[x + 16] - b.y,
                                      P[x + 17] - b.z, P[x + 18] - b.w);
        }
        __syncwarp();
    }

    // Chroma rows from smem staging
    #pragma unroll
    for (int r = 0; r < 2; ++r) {
        const float* R = r ? V : U;
        if (lane < 8) P[lane] = 0.f;
        float carry = 0.f;
        #pragma unroll
        for (int c = 0; c < 2; ++c) {
            float4 v = ((const float4*)R)[c * 32 + lane];
            float p1 = v.x + v.y, p2 = p1 + v.z, p3 = p2 + v.w;
            float tt = p3;
            #pragma unroll
            for (int off = 1; off < 32; off <<= 1) {
                float o = __shfl_up_sync(FULL, tt, off);
                if (lane >= off) tt += o;
            }
            float bb = tt - p3 + carry;
            ((float4*)(P + 8))[c * 32 + lane] =
                make_float4(bb + v.x, bb + p1, bb + p2, bb + p3);
            carry += __shfl_sync(FULL, tt, 31);
        }
        __syncwarp();
        if (lane < 7) P[8 + WQ + lane] = carry;
        __syncwarp();
        float4* dst = (float4*)(g_ch + ((long)(r * NB + n) * HQ + hq) * WQ);
        #pragma unroll
        for (int c = 0; c < 2; ++c) {
            int x = c * 128 + 4 * lane;
            float4 b = ((const float4*)P)[x >> 2];
            dst[x >> 2] = make_float4(P[x + 15] - b.x, P[x + 16] - b.y,
                                      P[x + 17] - b.z, P[x + 18] - b.w);
        }
        __syncwarp();
    }
}

// ---------------------------------------------------------------------------
// k_v: vertical 15-tap box (zero-pad SAME) via register sliding window,
// fused square + global reduce + finalize. No stores except accumulators.
// RGRP=16 rows per thread -> 384 blocks (4x the parallelism of R4).
// Blocks 0..255: Y (thread = 4 cols x 16 rows). Blocks 256..383: chroma.
// ---------------------------------------------------------------------------
#define NBLK_V 384
#define RGRP 16
__global__ void __launch_bounds__(256)
k_v(float* __restrict__ out) {
    __shared__ double red[8];
    const unsigned FULL = 0xFFFFFFFFu;

    int t = blockIdx.x * 256 + threadIdx.x;
    bool isY = t < 65536;

    const float* src; int H, y0; long stride;
    if (isY) {
        int colg = t & 127, rowg = (t >> 7) & 31, n = t >> 12;
        H = HH; stride = WW; y0 = rowg * RGRP;
        src = g_yh + (long)n * HH * WW + 4 * colg;
    } else {
        int t2 = t - 65536;
        int colg = t2 & 63, rowg = (t2 >> 6) & 15, pl = t2 >> 10;  // 0..31
        H = HQ; stride = WQ; y0 = rowg * RGRP;
        src = g_ch + (long)pl * HQ * WQ + 4 * colg;
    }

    float4 sum = make_float4(0.f, 0.f, 0.f, 0.f);
    #pragma unroll
    for (int d = -RAD; d <= RAD; ++d) {
        int yy = y0 + d;
        if (yy >= 0 && yy < H) {
            float4 v = *(const float4*)(src + (long)yy * stride);
            sum.x += v.x; sum.y += v.y; sum.z += v.z; sum.w += v.w;
        }
    }
    float racc = 0.f;
    #pragma unroll
    for (int i = 0; i < RGRP; ++i) {
        int y = y0 + i;
        racc += sum.x*sum.x + sum.y*sum.y + sum.z*sum.z + sum.w*sum.w;
        int ya = y + RAD + 1, yr = y - RAD;
        if (ya < H) {
            float4 v = *(const float4*)(src + (long)ya * stride);
            sum.x += v.x; sum.y += v.y; sum.z += v.z; sum.w += v.w;
        }
        if (yr >= 0) {
            float4 v = *(const float4*)(src + (long)yr * stride);
            sum.x -= v.x; sum.y -= v.y; sum.z -= v.z; sum.w -= v.w;
        }
    }
    double dacc = (double)racc;

    #pragma unroll
    for (int off = 16; off > 0; off >>= 1)
        dacc += __shfl_down_sync(FULL, dacc, off);
    int warp = threadIdx.x >> 5, lane = threadIdx.x & 31;
    if (lane == 0) red[warp] = dacc;
    __syncthreads();
    if (threadIdx.x == 0) {
        double s = 0.0;
        #pragma unroll
        for (int w = 0; w < 8; ++w) s += red[w];
        atomicAdd(&g_acc[isY ? 0 : 1], s);
        __threadfence();
        unsigned int prev = atomicAdd(&g_done, 1u);
        if (prev == NBLK_V - 1) {
            volatile double* acc = g_acc;
            double y = acc[0] / (double)((long)NB * HH * WW);
            double c = acc[1] / (double)((long)NB * HQ * WQ);
            out[0] = (float)(y + c);
            g_done = 0u;
        }
    }
}

extern "C" void kernel_launch(void* const* d_in, const int* in_sizes, int n_in,
                              void* d_out, int out_size) {
    const float* in = (const float*)d_in[0];
    const float* tg = (const float*)d_in[1];
    float* out = (float*)d_out;
    (void)in_sizes; (void)n_in; (void)out_size;

    k_diff_h<<<512, 256>>>(in, tg);
    k_v<<<NBLK_V, 256>>>(out);
}